// round 1
// baseline (speedup 1.0000x reference)
#include <cuda_runtime.h>
#include <cstdint>

// ---------------- problem dims ----------------
#define BB   8
#define PP   196
#define LL   80
#define DIM1 2048
#define DIM2 300
#define ATTD 1024

// ---------------- scratch (no allocations allowed) ----------------
__device__ float g_p1[BB * PP * ATTD];   // 6.4 MB
__device__ float g_p2[BB * LL * ATTD];   // 2.6 MB  (pre-scaled by 2*log2e)
__device__ float g_v [ATTD];
__device__ float g_c0[1];

// ---------------- packed f32x2 helpers ----------------
__device__ __forceinline__ unsigned long long pack2(float x, float y) {
    unsigned long long r;
    asm("mov.b64 %0, {%1, %2};" : "=l"(r) : "f"(x), "f"(y));
    return r;
}
__device__ __forceinline__ void fma2(unsigned long long& d, unsigned long long a, unsigned long long b) {
    asm("fma.rn.f32x2 %0, %1, %2, %0;" : "+l"(d) : "l"(a), "l"(b));
}
__device__ __forceinline__ float2 unpack2(unsigned long long v) {
    float2 f;
    asm("mov.b64 {%0, %1}, %2;" : "=f"(f.x), "=f"(f.y) : "l"(v));
    return f;
}

// tanh(x_raw) where input x = 2*log2e*x_raw already applied.
// t = 1 - 2 * rcp(ex2(x) + 1); handles +-inf saturation exactly.
__device__ __forceinline__ float tanh_pre(float x) {
    float e;
    asm("ex2.approx.f32 %0, %1;" : "=f"(e) : "f"(x));
    float d = e + 1.0f;
    float r;
    asm("rcp.approx.f32 %0, %1;" : "=f"(r) : "f"(d));
    return fmaf(-2.0f, r, 1.0f);
}

// ---------------- K0a: v[a] = sum_c wt[c] * Wh[c][a] ----------------
__global__ void k_v(const float* __restrict__ Wh, const float* __restrict__ wt) {
    int a = blockIdx.x * blockDim.x + threadIdx.x;   // 0..1023
    float s = 0.0f;
    #pragma unroll 8
    for (int c = 0; c < ATTD; c++)
        s = fmaf(wt[c], Wh[c * ATTD + a], s);
    g_v[a] = s;
}

// ---------------- K0b: c0 = wt . bh + bt ----------------
__global__ void k_c0(const float* __restrict__ wt, const float* __restrict__ bh,
                     const float* __restrict__ bt) {
    __shared__ float red[256];
    int t = threadIdx.x;
    float s = 0.0f;
    for (int c = t; c < ATTD; c += 256) s = fmaf(wt[c], bh[c], s);
    red[t] = s;
    __syncthreads();
    for (int off = 128; off > 0; off >>= 1) {
        if (t < off) red[t] += red[t + off];
        __syncthreads();
    }
    if (t == 0) g_c0[0] = red[0] + bt[0];
}

// ---------------- GEMM: C[m][n] = scale * sum_k A[m][k]*B[n][k] ----------------
// A: MxK row-major, B: 1024xK row-major, C: Mx1024 row-major (device scratch).
#define BM 64
#define BN 64
#define BKG 16

__global__ void __launch_bounds__(128) gemm_nt(const float* __restrict__ A,
                                               const float* __restrict__ B,
                                               int M, int K, float scale, int which) {
    __shared__ float As[BKG][BM + 4];
    __shared__ float Bs[BKG][BN + 4];
    float* C = which ? g_p2 : g_p1;

    int tid = threadIdx.x;
    int tx = tid & 7;        // n group: n0 = tx*8
    int ty = tid >> 3;       // m group: m0 = ty*4
    int mBase = blockIdx.x * BM;
    int nBase = blockIdx.y * BN;

    unsigned long long acc[4][4];
    #pragma unroll
    for (int i = 0; i < 4; i++)
        #pragma unroll
        for (int j = 0; j < 4; j++) acc[i][j] = 0ULL;

    for (int kc = 0; kc < K; kc += BKG) {
        // load A tile (64 rows x 16 k) transposed into As[k][m]
        #pragma unroll
        for (int i = 0; i < 2; i++) {
            int idx = tid + i * 128;         // 0..255 over 64x4 float4s
            int r   = idx >> 2;              // row 0..63
            int kq  = (idx & 3) * 4;         // 0,4,8,12
            int gm  = mBase + r;
            int gk  = kc + kq;
            float4 v = make_float4(0.f, 0.f, 0.f, 0.f);
            if (gm < M) {
                if (gk + 3 < K) {
                    v = *(const float4*)(A + (size_t)gm * K + gk);
                } else {
                    float tmp[4] = {0.f, 0.f, 0.f, 0.f};
                    #pragma unroll
                    for (int j = 0; j < 4; j++)
                        if (gk + j < K) tmp[j] = A[(size_t)gm * K + gk + j];
                    v = make_float4(tmp[0], tmp[1], tmp[2], tmp[3]);
                }
            }
            As[kq + 0][r] = v.x; As[kq + 1][r] = v.y;
            As[kq + 2][r] = v.z; As[kq + 3][r] = v.w;
        }
        // load B tile (64 rows x 16 k) transposed into Bs[k][n]; n always < 1024
        #pragma unroll
        for (int i = 0; i < 2; i++) {
            int idx = tid + i * 128;
            int r   = idx >> 2;
            int kq  = (idx & 3) * 4;
            int gn  = nBase + r;
            int gk  = kc + kq;
            float4 v = make_float4(0.f, 0.f, 0.f, 0.f);
            if (gk + 3 < K) {
                v = *(const float4*)(B + (size_t)gn * K + gk);
            } else {
                float tmp[4] = {0.f, 0.f, 0.f, 0.f};
                #pragma unroll
                for (int j = 0; j < 4; j++)
                    if (gk + j < K) tmp[j] = B[(size_t)gn * K + gk + j];
                v = make_float4(tmp[0], tmp[1], tmp[2], tmp[3]);
            }
            Bs[kq + 0][r] = v.x; Bs[kq + 1][r] = v.y;
            Bs[kq + 2][r] = v.z; Bs[kq + 3][r] = v.w;
        }
        __syncthreads();

        #pragma unroll
        for (int k = 0; k < BKG; k++) {
            float4 a4 = *(const float4*)&As[k][ty * 4];
            float4 b0 = *(const float4*)&Bs[k][tx * 8];
            float4 b1 = *(const float4*)&Bs[k][tx * 8 + 4];
            unsigned long long bb[4];
            bb[0] = pack2(b0.x, b0.y); bb[1] = pack2(b0.z, b0.w);
            bb[2] = pack2(b1.x, b1.y); bb[3] = pack2(b1.z, b1.w);
            float am[4] = {a4.x, a4.y, a4.z, a4.w};
            #pragma unroll
            for (int i = 0; i < 4; i++) {
                unsigned long long aa = pack2(am[i], am[i]);
                fma2(acc[i][0], aa, bb[0]);
                fma2(acc[i][1], aa, bb[1]);
                fma2(acc[i][2], aa, bb[2]);
                fma2(acc[i][3], aa, bb[3]);
            }
        }
        __syncthreads();
    }

    // epilogue
    #pragma unroll
    for (int i = 0; i < 4; i++) {
        int m = mBase + ty * 4 + i;
        if (m < M) {
            float* crow = C + (size_t)m * ATTD + nBase + tx * 8;
            #pragma unroll
            for (int j = 0; j < 4; j++) {
                float2 f = unpack2(acc[i][j]);
                crow[j * 2 + 0] = f.x * scale;
                crow[j * 2 + 1] = f.y * scale;
            }
        }
    }
}

// ---------------- fused: alpha[b,l,p] = sum_a tanh(p1*p2)*v[a] + c0 ----------------
#define TPp 32    // p per tile
#define TLl 16    // l per tile
#define CAa 64    // a chunk

__global__ void __launch_bounds__(128) fused_kernel(float* __restrict__ out) {
    __shared__ float sp1[TPp][CAa + 4];
    __shared__ float sp2[TLl][CAa + 4];
    __shared__ float sv[CAa];

    int tid = threadIdx.x;
    int tx = tid & 15;       // -> p pair (2*tx, 2*tx+1)
    int ty = tid >> 4;       // 0..7 -> l pair (2*ty, 2*ty+1)
    int b  = blockIdx.z;
    int l0 = blockIdx.y * TLl;
    int p0 = blockIdx.x * TPp;

    float acc00 = 0.f, acc01 = 0.f, acc10 = 0.f, acc11 = 0.f;

    for (int a0 = 0; a0 < ATTD; a0 += CAa) {
        // sp1: 32 rows x 64 a  (512 float4 / 128 thr = 4 each)
        #pragma unroll
        for (int i = 0; i < 4; i++) {
            int idx = tid + i * 128;
            int r = idx >> 4;            // 0..31
            int c = (idx & 15) * 4;      // 0..60
            int gp = p0 + r;
            float4 v = make_float4(0.f, 0.f, 0.f, 0.f);
            if (gp < PP)
                v = *(const float4*)(g_p1 + ((b * PP + gp) << 10) + a0 + c);
            *(float4*)&sp1[r][c] = v;
        }
        // sp2: 16 rows x 64 a  (256 float4 / 128 thr = 2 each); l always valid
        #pragma unroll
        for (int i = 0; i < 2; i++) {
            int idx = tid + i * 128;
            int r = idx >> 4;            // 0..15
            int c = (idx & 15) * 4;
            float4 v = *(const float4*)(g_p2 + ((b * LL + l0 + r) << 10) + a0 + c);
            *(float4*)&sp2[r][c] = v;
        }
        if (tid < 16)
            *(float4*)&sv[tid * 4] = *(const float4*)(g_v + a0 + tid * 4);
        __syncthreads();

        #pragma unroll 8
        for (int k = 0; k < CAa; k++) {
            float vv = sv[k];
            float q0 = sp2[2 * ty][k];
            float q1 = sp2[2 * ty + 1][k];
            float r0 = sp1[2 * tx][k];
            float r1 = sp1[2 * tx + 1][k];
            acc00 = fmaf(vv, tanh_pre(q0 * r0), acc00);
            acc01 = fmaf(vv, tanh_pre(q0 * r1), acc01);
            acc10 = fmaf(vv, tanh_pre(q1 * r0), acc10);
            acc11 = fmaf(vv, tanh_pre(q1 * r1), acc11);
        }
        __syncthreads();
    }

    float c0 = g_c0[0];
    int pA = p0 + 2 * tx;
    int lA = l0 + 2 * ty;
    float res[2][2] = {{acc00, acc01}, {acc10, acc11}};
    #pragma unroll
    for (int il = 0; il < 2; il++) {
        #pragma unroll
        for (int ip = 0; ip < 2; ip++) {
            int p = pA + ip;
            int l = lA + il;
            if (p < PP)
                out[(b * LL + l) * PP + p] = res[il][ip] + c0;
        }
    }
}

// ---------------- launch ----------------
extern "C" void kernel_launch(void* const* d_in, const int* in_sizes, int n_in,
                              void* d_out, int out_size) {
    const float* x1 = (const float*)d_in[0];
    const float* x2 = (const float*)d_in[1];
    const float* W1 = (const float*)d_in[2];
    const float* W2 = (const float*)d_in[3];
    const float* Wh = (const float*)d_in[4];
    const float* bh = (const float*)d_in[5];
    const float* wt = (const float*)d_in[6];
    const float* bt = (const float*)d_in[7];
    float* out = (float*)d_out;

    // v and c0
    k_v<<<4, 256>>>(Wh, wt);
    k_c0<<<1, 256>>>(wt, bh, bt);

    // p1 = x1 @ W1^T : M = B*P = 1568, K = 2048
    {
        dim3 grid((BB * PP + BM - 1) / BM, ATTD / BN);
        gemm_nt<<<grid, 128>>>(x1, W1, BB * PP, DIM1, 1.0f, 0);
    }
    // p2 = (2*log2e) * x2 @ W2^T : M = B*L = 640, K = 300
    {
        dim3 grid((BB * LL + BM - 1) / BM, ATTD / BN);
        gemm_nt<<<grid, 128>>>(x2, W2, BB * LL, DIM2, 2.8853900817779268f, 1);
    }
    // fused bilinear tanh reduce
    {
        dim3 grid((PP + TPp - 1) / TPp, LL / TLl, BB);
        fused_kernel<<<grid, 128>>>(out);
    }
}

// round 3
// speedup vs baseline: 1.9116x; 1.9116x over previous
#include <cuda_runtime.h>
#include <cuda_bf16.h>
#include <cstdint>

// ---------------- problem dims ----------------
#define BB   8
#define PP   196
#define LL   80
#define DIM1 2048
#define DIM2 300
#define ATTD 1024
#define M1   (BB * PP)      // 1568
#define M2   (BB * LL)      // 640

// ---------------- scratch (no allocations allowed) ----------------
__device__ float g_p1[M1 * ATTD];        // 6.4 MB
__device__ float g_p2[M2 * ATTD];        // 2.6 MB (pre-scaled by 2*log2e)
__device__ float g_v [ATTD];
__device__ float g_c0[1];
__device__ __nv_bfloat16 g_x1hi[M1 * DIM1];
__device__ __nv_bfloat16 g_x1lo[M1 * DIM1];
__device__ __nv_bfloat16 g_w1hi[ATTD * DIM1];
__device__ __nv_bfloat16 g_w1lo[ATTD * DIM1];

// ---------------- small helpers ----------------
__device__ __forceinline__ unsigned long long pack2(float x, float y) {
    unsigned long long r;
    asm("mov.b64 %0, {%1, %2};" : "=l"(r) : "f"(x), "f"(y));
    return r;
}
__device__ __forceinline__ void fma2(unsigned long long& d, unsigned long long a, unsigned long long b) {
    asm("fma.rn.f32x2 %0, %1, %2, %0;" : "+l"(d) : "l"(a), "l"(b));
}
__device__ __forceinline__ float2 unpack2(unsigned long long v) {
    float2 f;
    asm("mov.b64 {%0, %1}, %2;" : "=f"(f.x), "=f"(f.y) : "l"(v));
    return f;
}
__device__ __forceinline__ float tanh_pre(float x) {  // input pre-scaled by 2*log2e
    float e;
    asm("ex2.approx.f32 %0, %1;" : "=f"(e) : "f"(x));
    float d = e + 1.0f;
    float r;
    asm("rcp.approx.f32 %0, %1;" : "=f"(r) : "f"(d));
    return fmaf(-2.0f, r, 1.0f);
}
__device__ __forceinline__ uint32_t smem_u32(const void* p) {
    uint32_t a;
    asm("{ .reg .u64 t; cvta.to.shared.u64 t, %1; cvt.u32.u64 %0, t; }" : "=r"(a) : "l"(p));
    return a;
}
__device__ __forceinline__ void cp16(uint32_t dst, const void* src) {
    asm volatile("cp.async.ca.shared.global [%0], [%1], 16;" :: "r"(dst), "l"(src));
}
__device__ __forceinline__ void cp_commit() {
    asm volatile("cp.async.commit_group;" ::: "memory");
}
__device__ __forceinline__ void cp_wait1() {
    asm volatile("cp.async.wait_group 1;" ::: "memory");
}
__device__ __forceinline__ void ldmx4(uint32_t& r0, uint32_t& r1, uint32_t& r2, uint32_t& r3,
                                      uint32_t addr) {
    asm volatile("ldmatrix.sync.aligned.m8n8.x4.shared.b16 {%0,%1,%2,%3}, [%4];"
                 : "=r"(r0), "=r"(r1), "=r"(r2), "=r"(r3) : "r"(addr));
}
__device__ __forceinline__ void mma_bf16(float& d0, float& d1, float& d2, float& d3,
                                         uint32_t a0, uint32_t a1, uint32_t a2, uint32_t a3,
                                         uint32_t b0, uint32_t b1) {
    asm volatile("mma.sync.aligned.m16n8k16.row.col.f32.bf16.bf16.f32 "
                 "{%0,%1,%2,%3}, {%4,%5,%6,%7}, {%8,%9}, {%0,%1,%2,%3};"
                 : "+f"(d0), "+f"(d1), "+f"(d2), "+f"(d3)
                 : "r"(a0), "r"(a1), "r"(a2), "r"(a3), "r"(b0), "r"(b1));
}

// ---------------- split fp32 -> bf16 hi/lo ----------------
__global__ void k_split(const float* __restrict__ src,
                        __nv_bfloat16* __restrict__ hi,
                        __nv_bfloat16* __restrict__ lo, int n4) {
    int i = blockIdx.x * blockDim.x + threadIdx.x;
    if (i >= n4) return;
    float4 v = ((const float4*)src)[i];
    __nv_bfloat16 h0 = __float2bfloat16(v.x);
    __nv_bfloat16 h1 = __float2bfloat16(v.y);
    __nv_bfloat16 h2 = __float2bfloat16(v.z);
    __nv_bfloat16 h3 = __float2bfloat16(v.w);
    __nv_bfloat16 l0 = __float2bfloat16(v.x - __bfloat162float(h0));
    __nv_bfloat16 l1 = __float2bfloat16(v.y - __bfloat162float(h1));
    __nv_bfloat16 l2 = __float2bfloat16(v.z - __bfloat162float(h2));
    __nv_bfloat16 l3 = __float2bfloat16(v.w - __bfloat162float(h3));
    ushort4 ph = make_ushort4(__bfloat16_as_ushort(h0), __bfloat16_as_ushort(h1),
                              __bfloat16_as_ushort(h2), __bfloat16_as_ushort(h3));
    ushort4 pl = make_ushort4(__bfloat16_as_ushort(l0), __bfloat16_as_ushort(l1),
                              __bfloat16_as_ushort(l2), __bfloat16_as_ushort(l3));
    ((ushort4*)hi)[i] = ph;
    ((ushort4*)lo)[i] = pl;
}

// ---------------- K0a: v[a] = sum_c wt[c] * Wh[c][a] ----------------
__global__ void k_v(const float* __restrict__ Wh, const float* __restrict__ wt) {
    int a = blockIdx.x * blockDim.x + threadIdx.x;
    float s = 0.0f;
    #pragma unroll 8
    for (int c = 0; c < ATTD; c++)
        s = fmaf(wt[c], Wh[c * ATTD + a], s);
    g_v[a] = s;
}

// ---------------- K0b: c0 = wt . bh + bt ----------------
__global__ void k_c0(const float* __restrict__ wt, const float* __restrict__ bh,
                     const float* __restrict__ bt) {
    __shared__ float red[256];
    int t = threadIdx.x;
    float s = 0.0f;
    for (int c = t; c < ATTD; c += 256) s = fmaf(wt[c], bh[c], s);
    red[t] = s;
    __syncthreads();
    for (int off = 128; off > 0; off >>= 1) {
        if (t < off) red[t] += red[t + off];
        __syncthreads();
    }
    if (t == 0) g_c0[0] = red[0] + bt[0];
}

// ---------------- gemm2 (SIMT f32x2): p2 = scale * x2 @ W2^T ----------------
__global__ void __launch_bounds__(128) gemm2_k(const float* __restrict__ A,
                                               const float* __restrict__ B) {
    __shared__ float As[16][36];
    __shared__ float Bs[16][68];
    const float scale = 2.8853900817779268f;   // 2*log2(e)

    int tid = threadIdx.x;
    int tx = tid & 15;
    int ty = tid >> 4;
    int mBase = blockIdx.x * 32;
    int nBase = blockIdx.y * 64;

    unsigned long long acc[4][2];
    #pragma unroll
    for (int i = 0; i < 4; i++) { acc[i][0] = 0ULL; acc[i][1] = 0ULL; }

    for (int kc = 0; kc < DIM2; kc += 16) {
        {
            int r = tid >> 2, kq = (tid & 3) * 4;
            int gm = mBase + r, gk = kc + kq;
            float4 v = make_float4(0.f, 0.f, 0.f, 0.f);
            if (gk + 3 < DIM2) v = *(const float4*)(A + (size_t)gm * DIM2 + gk);
            else {
                float tmp[4] = {0.f, 0.f, 0.f, 0.f};
                #pragma unroll
                for (int j = 0; j < 4; j++)
                    if (gk + j < DIM2) tmp[j] = A[(size_t)gm * DIM2 + gk + j];
                v = make_float4(tmp[0], tmp[1], tmp[2], tmp[3]);
            }
            As[kq + 0][r] = v.x; As[kq + 1][r] = v.y;
            As[kq + 2][r] = v.z; As[kq + 3][r] = v.w;
        }
        #pragma unroll
        for (int i = 0; i < 2; i++) {
            int idx = tid + i * 128;
            int r = idx >> 2, kq = (idx & 3) * 4;
            int gn = nBase + r, gk = kc + kq;
            float4 v = make_float4(0.f, 0.f, 0.f, 0.f);
            if (gk + 3 < DIM2) v = *(const float4*)(B + (size_t)gn * DIM2 + gk);
            else {
                float tmp[4] = {0.f, 0.f, 0.f, 0.f};
                #pragma unroll
                for (int j = 0; j < 4; j++)
                    if (gk + j < DIM2) tmp[j] = B[(size_t)gn * DIM2 + gk + j];
                v = make_float4(tmp[0], tmp[1], tmp[2], tmp[3]);
            }
            Bs[kq + 0][r] = v.x; Bs[kq + 1][r] = v.y;
            Bs[kq + 2][r] = v.z; Bs[kq + 3][r] = v.w;
        }
        __syncthreads();

        #pragma unroll
        for (int k = 0; k < 16; k++) {
            float4 a4 = *(const float4*)&As[k][ty * 4];
            float4 b4 = *(const float4*)&Bs[k][tx * 4];
            unsigned long long b0 = pack2(b4.x, b4.y);
            unsigned long long b1 = pack2(b4.z, b4.w);
            float am[4] = {a4.x, a4.y, a4.z, a4.w};
            #pragma unroll
            for (int i = 0; i < 4; i++) {
                unsigned long long aa = pack2(am[i], am[i]);
                fma2(acc[i][0], aa, b0);
                fma2(acc[i][1], aa, b1);
            }
        }
        __syncthreads();
    }

    #pragma unroll
    for (int i = 0; i < 4; i++) {
        int m = mBase + ty * 4 + i;
        float* crow = g_p2 + (size_t)m * ATTD + nBase + tx * 4;
        float2 f0 = unpack2(acc[i][0]);
        float2 f1 = unpack2(acc[i][1]);
        crow[0] = f0.x * scale; crow[1] = f0.y * scale;
        crow[2] = f1.x * scale; crow[3] = f1.y * scale;
    }
}

// ---------------- gemm1: mma.sync bf16 3-term split, p1 = x1 @ W1^T ----------------
// BM=128, BN=64, BK=32, 256 threads (8 warps, 4m x 2n), warp tile 32x32.
// Smem rows padded to 80 B (32 bf16 = 64 B data + 16 B pad): conflict-free for
// ldmatrix (A) and direct lds.b32 (B).
#define G1_ROWB   80
#define G1_AHI    0
#define G1_ALO    10240
#define G1_BHI    20480
#define G1_BLO    25600
#define G1_STAGE  30720
#define G1_SMEM   (2 * G1_STAGE)
#define G1_NITER  (DIM1 / 32)     // 64

__global__ void __launch_bounds__(256) gemm1_tc() {
    extern __shared__ __align__(128) char sm[];
    const uint32_t smb = smem_u32(sm);
    const int tid  = threadIdx.x;
    const int lane = tid & 31;
    const int warp = tid >> 5;
    const int wm = warp >> 1;          // 0..3
    const int wn = warp & 1;           // 0..1
    const int mBase = blockIdx.x * 128;
    const int nBase = blockIdx.y * 64;

    // global src rows for the loads this thread performs
    // A: chunks id = tid + i*256 (i=0,1): row=id>>2 (0..127), cb=id&3
    int arow0 = mBase + (tid >> 2);
    int arow1 = mBase + ((tid + 256) >> 2);
    if (arow0 >= M1) arow0 = M1 - 1;
    if (arow1 >= M1) arow1 = M1 - 1;
    const int acb0 = tid & 3;
    const int acb1 = (tid + 256) & 3;
    const int brow = nBase + (tid >> 2);
    const int bcb  = tid & 3;

    auto load_stage = [&](int c, int st) {
        const int kc = c * 32;                       // bf16 element offset in K
        const uint32_t base = smb + st * G1_STAGE;
        // A hi/lo
        cp16(base + G1_AHI + (tid >> 2) * G1_ROWB + acb0 * 16,
             g_x1hi + (size_t)arow0 * DIM1 + kc + acb0 * 8);
        cp16(base + G1_AHI + ((tid + 256) >> 2) * G1_ROWB + acb1 * 16,
             g_x1hi + (size_t)arow1 * DIM1 + kc + acb1 * 8);
        cp16(base + G1_ALO + (tid >> 2) * G1_ROWB + acb0 * 16,
             g_x1lo + (size_t)arow0 * DIM1 + kc + acb0 * 8);
        cp16(base + G1_ALO + ((tid + 256) >> 2) * G1_ROWB + acb1 * 16,
             g_x1lo + (size_t)arow1 * DIM1 + kc + acb1 * 8);
        // B hi/lo (64 rows x 4 chunks = 256)
        cp16(base + G1_BHI + (tid >> 2) * G1_ROWB + bcb * 16,
             g_w1hi + (size_t)brow * DIM1 + kc + bcb * 8);
        cp16(base + G1_BLO + (tid >> 2) * G1_ROWB + bcb * 16,
             g_w1lo + (size_t)brow * DIM1 + kc + bcb * 8);
    };

    float acc[2][4][4];
    #pragma unroll
    for (int i = 0; i < 2; i++)
        #pragma unroll
        for (int j = 0; j < 4; j++)
            #pragma unroll
            for (int k = 0; k < 4; k++) acc[i][j][k] = 0.f;

    // prologue: stages 0 and 1
    load_stage(0, 0); cp_commit();
    load_stage(1, 1); cp_commit();

    // ldmatrix lane address components (A)
    const int lrow  = lane & 15;            // row within 16-row tile
    const int lcol  = (lane >> 4) * 16;     // 0 or 16 bytes
    // B lane address components
    const int bn    = lane >> 2;            // 0..7
    const int bk4   = (lane & 3) * 4;       // byte offset within k16

    for (int c = 0; c < G1_NITER; c++) {
        cp_wait1();
        __syncthreads();
        const uint32_t base = smb + (c & 1) * G1_STAGE;

        #pragma unroll
        for (int ks = 0; ks < 2; ks++) {
            const uint32_t kb = ks * 32;     // byte offset of this k16 within row
            // A fragments (hi, lo) for 2 m-tiles
            uint32_t ah[2][4], al[2][4];
            #pragma unroll
            for (int mt = 0; mt < 2; mt++) {
                uint32_t r = wm * 32 + mt * 16 + lrow;
                ldmx4(ah[mt][0], ah[mt][1], ah[mt][2], ah[mt][3],
                      base + G1_AHI + r * G1_ROWB + kb + lcol);
                ldmx4(al[mt][0], al[mt][1], al[mt][2], al[mt][3],
                      base + G1_ALO + r * G1_ROWB + kb + lcol);
            }
            // B fragments (hi, lo) for 4 n-tiles
            uint32_t bh[4][2], bl[4][2];
            #pragma unroll
            for (int nt = 0; nt < 4; nt++) {
                uint32_t r = wn * 32 + nt * 8 + bn;
                uint32_t a0 = base + G1_BHI + r * G1_ROWB + kb + bk4;
                uint32_t a1 = base + G1_BLO + r * G1_ROWB + kb + bk4;
                asm volatile("ld.shared.b32 %0, [%1];" : "=r"(bh[nt][0]) : "r"(a0));
                asm volatile("ld.shared.b32 %0, [%1];" : "=r"(bh[nt][1]) : "r"(a0 + 16));
                asm volatile("ld.shared.b32 %0, [%1];" : "=r"(bl[nt][0]) : "r"(a1));
                asm volatile("ld.shared.b32 %0, [%1];" : "=r"(bl[nt][1]) : "r"(a1 + 16));
            }
            #pragma unroll
            for (int mt = 0; mt < 2; mt++)
                #pragma unroll
                for (int nt = 0; nt < 4; nt++) {
                    float* d = acc[mt][nt];
                    mma_bf16(d[0], d[1], d[2], d[3],
                             ah[mt][0], ah[mt][1], ah[mt][2], ah[mt][3],
                             bh[nt][0], bh[nt][1]);
                    mma_bf16(d[0], d[1], d[2], d[3],
                             ah[mt][0], ah[mt][1], ah[mt][2], ah[mt][3],
                             bl[nt][0], bl[nt][1]);
                    mma_bf16(d[0], d[1], d[2], d[3],
                             al[mt][0], al[mt][1], al[mt][2], al[mt][3],
                             bh[nt][0], bh[nt][1]);
                }
        }
        __syncthreads();
        if (c + 2 < G1_NITER) load_stage(c + 2, c & 1);
        cp_commit();
    }

    // epilogue
    const int crow = (lane >> 2);
    const int ccol = (lane & 3) * 2;
    #pragma unroll
    for (int mt = 0; mt < 2; mt++) {
        int m0 = mBase + wm * 32 + mt * 16 + crow;
        #pragma unroll
        for (int nt = 0; nt < 4; nt++) {
            int n = nBase + wn * 32 + nt * 8 + ccol;
            if (m0 < M1)
                *(float2*)(g_p1 + (size_t)m0 * ATTD + n) = make_float2(acc[mt][nt][0], acc[mt][nt][1]);
            if (m0 + 8 < M1)
                *(float2*)(g_p1 + (size_t)(m0 + 8) * ATTD + n) = make_float2(acc[mt][nt][2], acc[mt][nt][3]);
        }
    }
}

// ---------------- fused: alpha[b,l,p] = sum_a tanh(p1*p2)*v[a] + c0 ----------------
#define TPp 32
#define TLl 16
#define CAa 64

__global__ void __launch_bounds__(128) fused_kernel(float* __restrict__ out) {
    __shared__ float sp1[TPp][CAa + 4];
    __shared__ float sp2[TLl][CAa + 4];
    __shared__ float sv[CAa];

    int tid = threadIdx.x;
    int tx = tid & 15;
    int ty = tid >> 4;
    int b  = blockIdx.z;
    int l0 = blockIdx.y * TLl;
    int p0 = blockIdx.x * TPp;

    float acc00 = 0.f, acc01 = 0.f, acc10 = 0.f, acc11 = 0.f;

    for (int a0 = 0; a0 < ATTD; a0 += CAa) {
        #pragma unroll
        for (int i = 0; i < 4; i++) {
            int idx = tid + i * 128;
            int r = idx >> 4;
            int c = (idx & 15) * 4;
            int gp = p0 + r;
            float4 v = make_float4(0.f, 0.f, 0.f, 0.f);
            if (gp < PP)
                v = *(const float4*)(g_p1 + ((b * PP + gp) << 10) + a0 + c);
            *(float4*)&sp1[r][c] = v;
        }
        #pragma unroll
        for (int i = 0; i < 2; i++) {
            int idx = tid + i * 128;
            int r = idx >> 4;
            int c = (idx & 15) * 4;
            float4 v = *(const float4*)(g_p2 + ((b * LL + l0 + r) << 10) + a0 + c);
            *(float4*)&sp2[r][c] = v;
        }
        if (tid < 16)
            *(float4*)&sv[tid * 4] = *(const float4*)(g_v + a0 + tid * 4);
        __syncthreads();

        #pragma unroll 8
        for (int k = 0; k < CAa; k++) {
            float vv = sv[k];
            float q0 = sp2[2 * ty][k];
            float q1 = sp2[2 * ty + 1][k];
            float r0 = sp1[2 * tx][k];
            float r1 = sp1[2 * tx + 1][k];
            acc00 = fmaf(vv, tanh_pre(q0 * r0), acc00);
            acc01 = fmaf(vv, tanh_pre(q0 * r1), acc01);
            acc10 = fmaf(vv, tanh_pre(q1 * r0), acc10);
            acc11 = fmaf(vv, tanh_pre(q1 * r1), acc11);
        }
        __syncthreads();
    }

    float c0 = g_c0[0];
    int pA = p0 + 2 * tx;
    int lA = l0 + 2 * ty;
    float res[2][2] = {{acc00, acc01}, {acc10, acc11}};
    #pragma unroll
    for (int il = 0; il < 2; il++)
        #pragma unroll
        for (int ip = 0; ip < 2; ip++) {
            int p = pA + ip;
            int l = lA + il;
            if (p < PP)
                out[(b * LL + l) * PP + p] = res[il][ip] + c0;
        }
}

// ---------------- launch ----------------
extern "C" void kernel_launch(void* const* d_in, const int* in_sizes, int n_in,
                              void* d_out, int out_size) {
    const float* x1 = (const float*)d_in[0];
    const float* x2 = (const float*)d_in[1];
    const float* W1 = (const float*)d_in[2];
    const float* W2 = (const float*)d_in[3];
    const float* Wh = (const float*)d_in[4];
    const float* bh = (const float*)d_in[5];
    const float* wt = (const float*)d_in[6];
    const float* bt = (const float*)d_in[7];
    float* out = (float*)d_out;

    static int smem_set = 0;
    if (!smem_set) {
        cudaFuncSetAttribute(gemm1_tc, cudaFuncAttributeMaxDynamicSharedMemorySize, G1_SMEM);
        smem_set = 1;
    }

    __nv_bfloat16 *x1hi, *x1lo, *w1hi, *w1lo;
    cudaGetSymbolAddress((void**)&x1hi, g_x1hi);
    cudaGetSymbolAddress((void**)&x1lo, g_x1lo);
    cudaGetSymbolAddress((void**)&w1hi, g_w1hi);
    cudaGetSymbolAddress((void**)&w1lo, g_w1lo);

    // 1,2: v and c0
    k_v<<<4, 256>>>(Wh, wt);
    k_c0<<<1, 256>>>(wt, bh, bt);
    // 3: p2 (SIMT)
    {
        dim3 grid(M2 / 32, ATTD / 64);
        gemm2_k<<<grid, 128>>>(x2, W2);
    }
    // 4,5: bf16 splits
    k_split<<<(M1 * DIM1 / 4 + 255) / 256, 256>>>(x1, x1hi, x1lo, M1 * DIM1 / 4);
    k_split<<<(ATTD * DIM1 / 4 + 255) / 256, 256>>>(W1, w1hi, w1lo, ATTD * DIM1 / 4);
    // 6: p1 via mma.sync (this is the ncu-profiled launch: -s 5 -c 1)
    {
        dim3 grid((M1 + 127) / 128, ATTD / 64);
        gemm1_tc<<<grid, 256, G1_SMEM>>>();
    }
    // 7: fused bilinear tanh reduce
    {
        dim3 grid((PP + TPp - 1) / TPp, LL / TLl, BB);
        fused_kernel<<<grid, 128>>>(out);
    }
}

// round 4
// speedup vs baseline: 1.9267x; 1.0079x over previous
#include <cuda_runtime.h>
#include <cuda_bf16.h>
#include <cstdint>

// ---------------- problem dims ----------------
#define BB   8
#define PP   196
#define LL   80
#define DIM1 2048
#define DIM2 300
#define ATTD 1024
#define M1   (BB * PP)      // 1568
#define M2   (BB * LL)      // 640

// ---------------- scratch (no allocations allowed) ----------------
__device__ float g_p1[M1 * ATTD];        // 6.4 MB
__device__ float g_p2[M2 * ATTD];        // 2.6 MB (pre-scaled by 2*log2e)
__device__ float g_v [ATTD];
__device__ float g_c0[1];
__device__ __nv_bfloat16 g_x1hi[M1 * DIM1];
__device__ __nv_bfloat16 g_x1lo[M1 * DIM1];
__device__ __nv_bfloat16 g_w1hi[ATTD * DIM1];
__device__ __nv_bfloat16 g_w1lo[ATTD * DIM1];

// ---------------- small helpers ----------------
__device__ __forceinline__ unsigned long long pack2(float x, float y) {
    unsigned long long r;
    asm("mov.b64 %0, {%1, %2};" : "=l"(r) : "f"(x), "f"(y));
    return r;
}
__device__ __forceinline__ void fma2(unsigned long long& d, unsigned long long a, unsigned long long b) {
    asm("fma.rn.f32x2 %0, %1, %2, %0;" : "+l"(d) : "l"(a), "l"(b));
}
__device__ __forceinline__ float2 unpack2(unsigned long long v) {
    float2 f;
    asm("mov.b64 {%0, %1}, %2;" : "=f"(f.x), "=f"(f.y) : "l"(v));
    return f;
}
__device__ __forceinline__ float tanh_pre(float x) {  // input pre-scaled by 2*log2e
    float e;
    asm("ex2.approx.f32 %0, %1;" : "=f"(e) : "f"(x));
    float d = e + 1.0f;
    float r;
    asm("rcp.approx.f32 %0, %1;" : "=f"(r) : "f"(d));
    return fmaf(-2.0f, r, 1.0f);
}
__device__ __forceinline__ uint32_t smem_u32(const void* p) {
    uint32_t a;
    asm("{ .reg .u64 t; cvta.to.shared.u64 t, %1; cvt.u32.u64 %0, t; }" : "=r"(a) : "l"(p));
    return a;
}
__device__ __forceinline__ void cp16(uint32_t dst, const void* src) {
    asm volatile("cp.async.ca.shared.global [%0], [%1], 16;" :: "r"(dst), "l"(src));
}
__device__ __forceinline__ void cp_commit() {
    asm volatile("cp.async.commit_group;" ::: "memory");
}
__device__ __forceinline__ void cp_wait1() {
    asm volatile("cp.async.wait_group 1;" ::: "memory");
}
__device__ __forceinline__ void ldmx4(uint32_t& r0, uint32_t& r1, uint32_t& r2, uint32_t& r3,
                                      uint32_t addr) {
    asm volatile("ldmatrix.sync.aligned.m8n8.x4.shared.b16 {%0,%1,%2,%3}, [%4];"
                 : "=r"(r0), "=r"(r1), "=r"(r2), "=r"(r3) : "r"(addr));
}
__device__ __forceinline__ void mma_bf16(float& d0, float& d1, float& d2, float& d3,
                                         uint32_t a0, uint32_t a1, uint32_t a2, uint32_t a3,
                                         uint32_t b0, uint32_t b1) {
    asm volatile("mma.sync.aligned.m16n8k16.row.col.f32.bf16.bf16.f32 "
                 "{%0,%1,%2,%3}, {%4,%5,%6,%7}, {%8,%9}, {%0,%1,%2,%3};"
                 : "+f"(d0), "+f"(d1), "+f"(d2), "+f"(d3)
                 : "r"(a0), "r"(a1), "r"(a2), "r"(a3), "r"(b0), "r"(b1));
}

// ---------------- launch 1: split fp32 -> bf16 hi/lo (x1 and W1 in one grid) ----
#define X1_BLKS (M1 * DIM1 / 4 / 256)     // 3136
#define W1_BLKS (ATTD * DIM1 / 4 / 256)   // 2048
__global__ void __launch_bounds__(256) k_split_all(const float* __restrict__ x1,
                                                   const float* __restrict__ W1) {
    int bid = blockIdx.x;
    const float* src;
    __nv_bfloat16 *hi, *lo;
    int i;
    if (bid < X1_BLKS) {
        src = x1; hi = g_x1hi; lo = g_x1lo;
        i = bid * 256 + threadIdx.x;
    } else {
        src = W1; hi = g_w1hi; lo = g_w1lo;
        i = (bid - X1_BLKS) * 256 + threadIdx.x;
    }
    float4 v = ((const float4*)src)[i];
    __nv_bfloat16 h0 = __float2bfloat16(v.x);
    __nv_bfloat16 h1 = __float2bfloat16(v.y);
    __nv_bfloat16 h2 = __float2bfloat16(v.z);
    __nv_bfloat16 h3 = __float2bfloat16(v.w);
    __nv_bfloat16 l0 = __float2bfloat16(v.x - __bfloat162float(h0));
    __nv_bfloat16 l1 = __float2bfloat16(v.y - __bfloat162float(h1));
    __nv_bfloat16 l2 = __float2bfloat16(v.z - __bfloat162float(h2));
    __nv_bfloat16 l3 = __float2bfloat16(v.w - __bfloat162float(h3));
    ushort4 ph = make_ushort4(__bfloat16_as_ushort(h0), __bfloat16_as_ushort(h1),
                              __bfloat16_as_ushort(h2), __bfloat16_as_ushort(h3));
    ushort4 pl = make_ushort4(__bfloat16_as_ushort(l0), __bfloat16_as_ushort(l1),
                              __bfloat16_as_ushort(l2), __bfloat16_as_ushort(l3));
    ((ushort4*)hi)[i] = ph;
    ((ushort4*)lo)[i] = pl;
}

// ---------------- launch 2: gemm2 (SIMT f32x2) + v + c0 folded ----------------
// grid (21, 16): x<20 -> gemm2 tile; x==20 -> v (64 a's per y), (20,0) warp2 -> c0
__global__ void __launch_bounds__(128) gemm2pre(const float* __restrict__ A,
                                                const float* __restrict__ B,
                                                const float* __restrict__ Wh,
                                                const float* __restrict__ wt,
                                                const float* __restrict__ bh,
                                                const float* __restrict__ bt) {
    if (blockIdx.x == 20) {
        int t = threadIdx.x;
        if (t < 64) {
            int a = blockIdx.y * 64 + t;
            float s = 0.0f;
            #pragma unroll 8
            for (int c = 0; c < ATTD; c++)
                s = fmaf(wt[c], Wh[c * ATTD + a], s);
            g_v[a] = s;
        } else if (blockIdx.y == 0 && t < 96) {   // whole warp 2
            int u = t - 64;
            float s = 0.0f;
            for (int j = u; j < ATTD; j += 32) s = fmaf(wt[j], bh[j], s);
            #pragma unroll
            for (int off = 16; off > 0; off >>= 1)
                s += __shfl_xor_sync(0xffffffffu, s, off);
            if (u == 0) g_c0[0] = s + bt[0];
        }
        return;
    }

    __shared__ float As[16][36];
    __shared__ float Bs[16][68];
    const float scale = 2.8853900817779268f;   // 2*log2(e)

    int tid = threadIdx.x;
    int tx = tid & 15;
    int ty = tid >> 4;
    int mBase = blockIdx.x * 32;
    int nBase = blockIdx.y * 64;

    unsigned long long acc[4][2];
    #pragma unroll
    for (int i = 0; i < 4; i++) { acc[i][0] = 0ULL; acc[i][1] = 0ULL; }

    for (int kc = 0; kc < DIM2; kc += 16) {
        {
            int r = tid >> 2, kq = (tid & 3) * 4;
            int gm = mBase + r, gk = kc + kq;
            float4 v = make_float4(0.f, 0.f, 0.f, 0.f);
            if (gk + 3 < DIM2) v = *(const float4*)(A + (size_t)gm * DIM2 + gk);
            else {
                float tmp[4] = {0.f, 0.f, 0.f, 0.f};
                #pragma unroll
                for (int j = 0; j < 4; j++)
                    if (gk + j < DIM2) tmp[j] = A[(size_t)gm * DIM2 + gk + j];
                v = make_float4(tmp[0], tmp[1], tmp[2], tmp[3]);
            }
            As[kq + 0][r] = v.x; As[kq + 1][r] = v.y;
            As[kq + 2][r] = v.z; As[kq + 3][r] = v.w;
        }
        #pragma unroll
        for (int i = 0; i < 2; i++) {
            int idx = tid + i * 128;
            int r = idx >> 2, kq = (idx & 3) * 4;
            int gn = nBase + r, gk = kc + kq;
            float4 v = make_float4(0.f, 0.f, 0.f, 0.f);
            if (gk + 3 < DIM2) v = *(const float4*)(B + (size_t)gn * DIM2 + gk);
            else {
                float tmp[4] = {0.f, 0.f, 0.f, 0.f};
                #pragma unroll
                for (int j = 0; j < 4; j++)
                    if (gk + j < DIM2) tmp[j] = B[(size_t)gn * DIM2 + gk + j];
                v = make_float4(tmp[0], tmp[1], tmp[2], tmp[3]);
            }
            Bs[kq + 0][r] = v.x; Bs[kq + 1][r] = v.y;
            Bs[kq + 2][r] = v.z; Bs[kq + 3][r] = v.w;
        }
        __syncthreads();

        #pragma unroll
        for (int k = 0; k < 16; k++) {
            float4 a4 = *(const float4*)&As[k][ty * 4];
            float4 b4 = *(const float4*)&Bs[k][tx * 4];
            unsigned long long b0 = pack2(b4.x, b4.y);
            unsigned long long b1 = pack2(b4.z, b4.w);
            float am[4] = {a4.x, a4.y, a4.z, a4.w};
            #pragma unroll
            for (int i = 0; i < 4; i++) {
                unsigned long long aa = pack2(am[i], am[i]);
                fma2(acc[i][0], aa, b0);
                fma2(acc[i][1], aa, b1);
            }
        }
        __syncthreads();
    }

    #pragma unroll
    for (int i = 0; i < 4; i++) {
        int m = mBase + ty * 4 + i;
        float* crow = g_p2 + (size_t)m * ATTD + nBase + tx * 4;
        float2 f0 = unpack2(acc[i][0]);
        float2 f1 = unpack2(acc[i][1]);
        crow[0] = f0.x * scale; crow[1] = f0.y * scale;
        crow[2] = f1.x * scale; crow[3] = f1.y * scale;
    }
}

// ---------------- launch 3: gemm1 mma.sync bf16 3-term split ----------------
#define G1_ROWB   80
#define G1_AHI    0
#define G1_ALO    10240
#define G1_BHI    20480
#define G1_BLO    25600
#define G1_STAGE  30720
#define G1_SMEM   (2 * G1_STAGE)
#define G1_NITER  (DIM1 / 32)     // 64

__global__ void __launch_bounds__(256) gemm1_tc() {
    extern __shared__ __align__(128) char sm[];
    const uint32_t smb = smem_u32(sm);
    const int tid  = threadIdx.x;
    const int lane = tid & 31;
    const int warp = tid >> 5;
    const int wm = warp >> 1;
    const int wn = warp & 1;
    const int mBase = blockIdx.x * 128;
    const int nBase = blockIdx.y * 64;

    int arow0 = mBase + (tid >> 2);
    int arow1 = mBase + ((tid + 256) >> 2);
    if (arow0 >= M1) arow0 = M1 - 1;
    if (arow1 >= M1) arow1 = M1 - 1;
    const int acb0 = tid & 3;
    const int acb1 = (tid + 256) & 3;
    const int brow = nBase + (tid >> 2);
    const int bcb  = tid & 3;

    auto load_stage = [&](int c, int st) {
        const int kc = c * 32;
        const uint32_t base = smb + st * G1_STAGE;
        cp16(base + G1_AHI + (tid >> 2) * G1_ROWB + acb0 * 16,
             g_x1hi + (size_t)arow0 * DIM1 + kc + acb0 * 8);
        cp16(base + G1_AHI + ((tid + 256) >> 2) * G1_ROWB + acb1 * 16,
             g_x1hi + (size_t)arow1 * DIM1 + kc + acb1 * 8);
        cp16(base + G1_ALO + (tid >> 2) * G1_ROWB + acb0 * 16,
             g_x1lo + (size_t)arow0 * DIM1 + kc + acb0 * 8);
        cp16(base + G1_ALO + ((tid + 256) >> 2) * G1_ROWB + acb1 * 16,
             g_x1lo + (size_t)arow1 * DIM1 + kc + acb1 * 8);
        cp16(base + G1_BHI + (tid >> 2) * G1_ROWB + bcb * 16,
             g_w1hi + (size_t)brow * DIM1 + kc + bcb * 8);
        cp16(base + G1_BLO + (tid >> 2) * G1_ROWB + bcb * 16,
             g_w1lo + (size_t)brow * DIM1 + kc + bcb * 8);
    };

    float acc[2][4][4];
    #pragma unroll
    for (int i = 0; i < 2; i++)
        #pragma unroll
        for (int j = 0; j < 4; j++)
            #pragma unroll
            for (int k = 0; k < 4; k++) acc[i][j][k] = 0.f;

    load_stage(0, 0); cp_commit();
    load_stage(1, 1); cp_commit();

    const int lrow  = lane & 15;
    const int lcol  = (lane >> 4) * 16;
    const int bn    = lane >> 2;
    const int bk4   = (lane & 3) * 4;

    for (int c = 0; c < G1_NITER; c++) {
        cp_wait1();
        __syncthreads();
        const uint32_t base = smb + (c & 1) * G1_STAGE;

        #pragma unroll
        for (int ks = 0; ks < 2; ks++) {
            const uint32_t kb = ks * 32;
            uint32_t ah[2][4], al[2][4];
            #pragma unroll
            for (int mt = 0; mt < 2; mt++) {
                uint32_t r = wm * 32 + mt * 16 + lrow;
                ldmx4(ah[mt][0], ah[mt][1], ah[mt][2], ah[mt][3],
                      base + G1_AHI + r * G1_ROWB + kb + lcol);
                ldmx4(al[mt][0], al[mt][1], al[mt][2], al[mt][3],
                      base + G1_ALO + r * G1_ROWB + kb + lcol);
            }
            uint32_t bhf[4][2], blf[4][2];
            #pragma unroll
            for (int nt = 0; nt < 4; nt++) {
                uint32_t r = wn * 32 + nt * 8 + bn;
                uint32_t a0 = base + G1_BHI + r * G1_ROWB + kb + bk4;
                uint32_t a1 = base + G1_BLO + r * G1_ROWB + kb + bk4;
                asm volatile("ld.shared.b32 %0, [%1];" : "=r"(bhf[nt][0]) : "r"(a0));
                asm volatile("ld.shared.b32 %0, [%1];" : "=r"(bhf[nt][1]) : "r"(a0 + 16));
                asm volatile("ld.shared.b32 %0, [%1];" : "=r"(blf[nt][0]) : "r"(a1));
                asm volatile("ld.shared.b32 %0, [%1];" : "=r"(blf[nt][1]) : "r"(a1 + 16));
            }
            #pragma unroll
            for (int mt = 0; mt < 2; mt++)
                #pragma unroll
                for (int nt = 0; nt < 4; nt++) {
                    float* d = acc[mt][nt];
                    mma_bf16(d[0], d[1], d[2], d[3],
                             ah[mt][0], ah[mt][1], ah[mt][2], ah[mt][3],
                             bhf[nt][0], bhf[nt][1]);
                    mma_bf16(d[0], d[1], d[2], d[3],
                             ah[mt][0], ah[mt][1], ah[mt][2], ah[mt][3],
                             blf[nt][0], blf[nt][1]);
                    mma_bf16(d[0], d[1], d[2], d[3],
                             al[mt][0], al[mt][1], al[mt][2], al[mt][3],
                             bhf[nt][0], bhf[nt][1]);
                }
        }
        __syncthreads();
        if (c + 2 < G1_NITER) load_stage(c + 2, c & 1);
        cp_commit();
    }

    const int crow = (lane >> 2);
    const int ccol = (lane & 3) * 2;
    #pragma unroll
    for (int mt = 0; mt < 2; mt++) {
        int m0 = mBase + wm * 32 + mt * 16 + crow;
        #pragma unroll
        for (int nt = 0; nt < 4; nt++) {
            int n = nBase + wn * 32 + nt * 8 + ccol;
            if (m0 < M1)
                *(float2*)(g_p1 + (size_t)m0 * ATTD + n) = make_float2(acc[mt][nt][0], acc[mt][nt][1]);
            if (m0 + 8 < M1)
                *(float2*)(g_p1 + (size_t)(m0 + 8) * ATTD + n) = make_float2(acc[mt][nt][2], acc[mt][nt][3]);
        }
    }
}

// ---------------- launch 4 (profiled): fused bilinear tanh reduce --------------
// alpha[b,l,p] = sum_a tanh(p1*p2)*v[a] + c0, transposed conflict-free tiles
#define TPp 32
#define TLl 16
#define CAa 64
#define SP1_STRIDE (TPp + 2)   // 34 floats (even -> 8B-aligned float2)
#define SP2_STRIDE (TLl + 2)   // 18 floats

__global__ void __launch_bounds__(128) fused_kernel(float* __restrict__ out) {
    __shared__ float sp1T[CAa][SP1_STRIDE];
    __shared__ float sp2T[CAa][SP2_STRIDE];
    __shared__ float sv[CAa];

    int tid = threadIdx.x;
    int tx = tid & 15;       // p pair (2tx, 2tx+1)
    int ty = tid >> 4;       // l pair (2ty, 2ty+1)
    int b  = blockIdx.z;
    int l0 = blockIdx.y * TLl;
    int p0 = blockIdx.x * TPp;

    float acc00 = 0.f, acc01 = 0.f, acc10 = 0.f, acc11 = 0.f;

    for (int a0 = 0; a0 < ATTD; a0 += CAa) {
        // sp1T[a][p]: 64a x 32p. idx -> a = idx&63 (coalesced global), p = idx>>6
        #pragma unroll
        for (int i = 0; i < 16; i++) {
            int idx = tid + i * 128;
            int a = idx & 63;
            int p = idx >> 6;
            int gp = p0 + p;
            float v = 0.f;
            if (gp < PP) v = g_p1[((b * PP + gp) << 10) + a0 + a];
            sp1T[a][p] = v;
        }
        // sp2T[a][l]: 64a x 16l
        #pragma unroll
        for (int i = 0; i < 8; i++) {
            int idx = tid + i * 128;
            int a = idx & 63;
            int l = idx >> 6;
            sp2T[a][l] = g_p2[((b * LL + l0 + l) << 10) + a0 + a];
        }
        if (tid < 64) sv[tid] = g_v[a0 + tid];
        __syncthreads();

        #pragma unroll 8
        for (int k = 0; k < CAa; k++) {
            float2 rr = *(const float2*)&sp1T[k][2 * tx];
            float2 qq = *(const float2*)&sp2T[k][2 * ty];
            float vv = sv[k];
            acc00 = fmaf(vv, tanh_pre(qq.x * rr.x), acc00);
            acc01 = fmaf(vv, tanh_pre(qq.x * rr.y), acc01);
            acc10 = fmaf(vv, tanh_pre(qq.y * rr.x), acc10);
            acc11 = fmaf(vv, tanh_pre(qq.y * rr.y), acc11);
        }
        __syncthreads();
    }

    float c0 = g_c0[0];
    int pA = p0 + 2 * tx;
    int lA = l0 + 2 * ty;
    float res[2][2] = {{acc00, acc01}, {acc10, acc11}};
    #pragma unroll
    for (int il = 0; il < 2; il++)
        #pragma unroll
        for (int ip = 0; ip < 2; ip++) {
            int p = pA + ip;
            int l = lA + il;
            if (p < PP)
                out[(b * LL + l) * PP + p] = res[il][ip] + c0;
        }
}

// ---------------- launch ----------------
extern "C" void kernel_launch(void* const* d_in, const int* in_sizes, int n_in,
                              void* d_out, int out_size) {
    const float* x1 = (const float*)d_in[0];
    const float* x2 = (const float*)d_in[1];
    const float* W1 = (const float*)d_in[2];
    const float* W2 = (const float*)d_in[3];
    const float* Wh = (const float*)d_in[4];
    const float* bh = (const float*)d_in[5];
    const float* wt = (const float*)d_in[6];
    const float* bt = (const float*)d_in[7];
    float* out = (float*)d_out;

    static int smem_set = 0;
    if (!smem_set) {
        cudaFuncSetAttribute(gemm1_tc, cudaFuncAttributeMaxDynamicSharedMemorySize, G1_SMEM);
        smem_set = 1;
    }

    // 1: bf16 splits (x1 + W1)
    k_split_all<<<X1_BLKS + W1_BLKS, 256>>>(x1, W1);
    // 2: p2 GEMM + v + c0
    {
        dim3 grid(21, ATTD / 64);
        gemm2pre<<<grid, 128>>>(x2, W2, Wh, wt, bh, bt);
    }
    // 3: p1 via mma.sync bf16 3-term
    {
        dim3 grid((M1 + 127) / 128, ATTD / 64);
        gemm1_tc<<<grid, 256, G1_SMEM>>>();
    }
    // 4: fused bilinear tanh reduce  (ncu-profiled slot)
    {
        dim3 grid((PP + TPp - 1) / TPp, LL / TLl, BB);
        fused_kernel<<<grid, 128>>>(out);
    }
}

// round 8
// speedup vs baseline: 2.2446x; 1.1650x over previous
#include <cuda_runtime.h>
#include <cuda_bf16.h>
#include <cstdint>

// ---------------- problem dims ----------------
#define BB   8
#define PP   196
#define LL   80
#define DIM1 2048
#define DIM2 300
#define ATTD 1024
#define M1   (BB * PP)      // 1568
#define M2   (BB * LL)      // 640
#define OUTN (BB * LL * PP) // 125440

// ---------------- scratch (no allocations allowed) ----------------
__device__ float g_p1[M1 * ATTD];        // 6.4 MB
__device__ float g_p2[M2 * ATTD];        // 2.6 MB (pre-scaled by 2*log2e)
__device__ float g_v [ATTD];
__device__ float g_c0[1];
__device__ __nv_bfloat16 g_x1hi[M1 * DIM1];
__device__ __nv_bfloat16 g_x1lo[M1 * DIM1];
__device__ __nv_bfloat16 g_w1hi[ATTD * DIM1];
__device__ __nv_bfloat16 g_w1lo[ATTD * DIM1];

// ---------------- small helpers ----------------
__device__ __forceinline__ unsigned long long pack2(float x, float y) {
    unsigned long long r;
    asm("mov.b64 %0, {%1, %2};" : "=l"(r) : "f"(x), "f"(y));
    return r;
}
__device__ __forceinline__ void fma2(unsigned long long& d, unsigned long long a, unsigned long long b) {
    asm("fma.rn.f32x2 %0, %1, %2, %0;" : "+l"(d) : "l"(a), "l"(b));
}
__device__ __forceinline__ float2 unpack2(unsigned long long v) {
    float2 f;
    asm("mov.b64 {%0, %1}, %2;" : "=f"(f.x), "=f"(f.y) : "l"(v));
    return f;
}
__device__ __forceinline__ uint32_t smem_u32(const void* p) {
    uint32_t a;
    asm("{ .reg .u64 t; cvta.to.shared.u64 t, %1; cvt.u32.u64 %0, t; }" : "=r"(a) : "l"(p));
    return a;
}
__device__ __forceinline__ void cp16(uint32_t dst, const void* src) {
    asm volatile("cp.async.ca.shared.global [%0], [%1], 16;" :: "r"(dst), "l"(src));
}
__device__ __forceinline__ void cp_commit() {
    asm volatile("cp.async.commit_group;" ::: "memory");
}
__device__ __forceinline__ void cp_wait1() {
    asm volatile("cp.async.wait_group 1;" ::: "memory");
}
__device__ __forceinline__ void ldmx4(uint32_t& r0, uint32_t& r1, uint32_t& r2, uint32_t& r3,
                                      uint32_t addr) {
    asm volatile("ldmatrix.sync.aligned.m8n8.x4.shared.b16 {%0,%1,%2,%3}, [%4];"
                 : "=r"(r0), "=r"(r1), "=r"(r2), "=r"(r3) : "r"(addr));
}
__device__ __forceinline__ void mma_bf16(float& d0, float& d1, float& d2, float& d3,
                                         uint32_t a0, uint32_t a1, uint32_t a2, uint32_t a3,
                                         uint32_t b0, uint32_t b1) {
    asm volatile("mma.sync.aligned.m16n8k16.row.col.f32.bf16.bf16.f32 "
                 "{%0,%1,%2,%3}, {%4,%5,%6,%7}, {%8,%9}, {%0,%1,%2,%3};"
                 : "+f"(d0), "+f"(d1), "+f"(d2), "+f"(d3)
                 : "r"(a0), "r"(a1), "r"(a2), "r"(a3), "r"(b0), "r"(b1));
}

// ---------------- launch 1: split fp32 -> bf16 hi/lo (x1 and W1 in one grid) ----
#define X1_BLKS (M1 * DIM1 / 4 / 256)     // 3136
#define W1_BLKS (ATTD * DIM1 / 4 / 256)   // 2048
__global__ void __launch_bounds__(256) k_split_all(const float* __restrict__ x1,
                                                   const float* __restrict__ W1) {
    int bid = blockIdx.x;
    const float* src;
    __nv_bfloat16 *hi, *lo;
    int i;
    if (bid < X1_BLKS) {
        src = x1; hi = g_x1hi; lo = g_x1lo;
        i = bid * 256 + threadIdx.x;
    } else {
        src = W1; hi = g_w1hi; lo = g_w1lo;
        i = (bid - X1_BLKS) * 256 + threadIdx.x;
    }
    float4 v = ((const float4*)src)[i];
    __nv_bfloat16 h0 = __float2bfloat16(v.x);
    __nv_bfloat16 h1 = __float2bfloat16(v.y);
    __nv_bfloat16 h2 = __float2bfloat16(v.z);
    __nv_bfloat16 h3 = __float2bfloat16(v.w);
    __nv_bfloat16 l0 = __float2bfloat16(v.x - __bfloat162float(h0));
    __nv_bfloat16 l1 = __float2bfloat16(v.y - __bfloat162float(h1));
    __nv_bfloat16 l2 = __float2bfloat16(v.z - __bfloat162float(h2));
    __nv_bfloat16 l3 = __float2bfloat16(v.w - __bfloat162float(h3));
    ushort4 ph = make_ushort4(__bfloat16_as_ushort(h0), __bfloat16_as_ushort(h1),
                              __bfloat16_as_ushort(h2), __bfloat16_as_ushort(h3));
    ushort4 pl = make_ushort4(__bfloat16_as_ushort(l0), __bfloat16_as_ushort(l1),
                              __bfloat16_as_ushort(l2), __bfloat16_as_ushort(l3));
    ((ushort4*)hi)[i] = ph;
    ((ushort4*)lo)[i] = pl;
}

// ---------------- launch 2: gemm2 (SIMT f32x2) + v + c0 folded ----------------
__global__ void __launch_bounds__(128) gemm2pre(const float* __restrict__ A,
                                                const float* __restrict__ B,
                                                const float* __restrict__ Wh,
                                                const float* __restrict__ wt,
                                                const float* __restrict__ bh,
                                                const float* __restrict__ bt) {
    if (blockIdx.x == 20) {
        int t = threadIdx.x;
        if (t < 64) {
            int a = blockIdx.y * 64 + t;
            float s = 0.0f;
            #pragma unroll 8
            for (int c = 0; c < ATTD; c++)
                s = fmaf(wt[c], Wh[c * ATTD + a], s);
            g_v[a] = s;
        } else if (blockIdx.y == 0 && t < 96) {
            int u = t - 64;
            float s = 0.0f;
            for (int j = u; j < ATTD; j += 32) s = fmaf(wt[j], bh[j], s);
            #pragma unroll
            for (int off = 16; off > 0; off >>= 1)
                s += __shfl_xor_sync(0xffffffffu, s, off);
            if (u == 0) g_c0[0] = s + bt[0];
        }
        return;
    }

    __shared__ float As[16][36];
    __shared__ float Bs[16][68];
    const float scale = 2.8853900817779268f;   // 2*log2(e)

    int tid = threadIdx.x;
    int tx = tid & 15;
    int ty = tid >> 4;
    int mBase = blockIdx.x * 32;
    int nBase = blockIdx.y * 64;

    unsigned long long acc[4][2];
    #pragma unroll
    for (int i = 0; i < 4; i++) { acc[i][0] = 0ULL; acc[i][1] = 0ULL; }

    for (int kc = 0; kc < DIM2; kc += 16) {
        {
            int r = tid >> 2, kq = (tid & 3) * 4;
            int gm = mBase + r, gk = kc + kq;
            float4 v = make_float4(0.f, 0.f, 0.f, 0.f);
            if (gk + 3 < DIM2) v = *(const float4*)(A + (size_t)gm * DIM2 + gk);
            else {
                float tmp[4] = {0.f, 0.f, 0.f, 0.f};
                #pragma unroll
                for (int j = 0; j < 4; j++)
                    if (gk + j < DIM2) tmp[j] = A[(size_t)gm * DIM2 + gk + j];
                v = make_float4(tmp[0], tmp[1], tmp[2], tmp[3]);
            }
            As[kq + 0][r] = v.x; As[kq + 1][r] = v.y;
            As[kq + 2][r] = v.z; As[kq + 3][r] = v.w;
        }
        #pragma unroll
        for (int i = 0; i < 2; i++) {
            int idx = tid + i * 128;
            int r = idx >> 2, kq = (idx & 3) * 4;
            int gn = nBase + r, gk = kc + kq;
            float4 v = make_float4(0.f, 0.f, 0.f, 0.f);
            if (gk + 3 < DIM2) v = *(const float4*)(B + (size_t)gn * DIM2 + gk);
            else {
                float tmp[4] = {0.f, 0.f, 0.f, 0.f};
                #pragma unroll
                for (int j = 0; j < 4; j++)
                    if (gk + j < DIM2) tmp[j] = B[(size_t)gn * DIM2 + gk + j];
                v = make_float4(tmp[0], tmp[1], tmp[2], tmp[3]);
            }
            Bs[kq + 0][r] = v.x; Bs[kq + 1][r] = v.y;
            Bs[kq + 2][r] = v.z; Bs[kq + 3][r] = v.w;
        }
        __syncthreads();

        #pragma unroll
        for (int k = 0; k < 16; k++) {
            float4 a4 = *(const float4*)&As[k][ty * 4];
            float4 b4 = *(const float4*)&Bs[k][tx * 4];
            unsigned long long b0 = pack2(b4.x, b4.y);
            unsigned long long b1 = pack2(b4.z, b4.w);
            float am[4] = {a4.x, a4.y, a4.z, a4.w};
            #pragma unroll
            for (int i = 0; i < 4; i++) {
                unsigned long long aa = pack2(am[i], am[i]);
                fma2(acc[i][0], aa, b0);
                fma2(acc[i][1], aa, b1);
            }
        }
        __syncthreads();
    }

    #pragma unroll
    for (int i = 0; i < 4; i++) {
        int m = mBase + ty * 4 + i;
        float* crow = g_p2 + (size_t)m * ATTD + nBase + tx * 4;
        float2 f0 = unpack2(acc[i][0]);
        float2 f1 = unpack2(acc[i][1]);
        crow[0] = f0.x * scale; crow[1] = f0.y * scale;
        crow[2] = f1.x * scale; crow[3] = f1.y * scale;
    }
}

// ---------------- launch 3: gemm1 mma.sync + out-init spare column ------------
#define G1_ROWB   80
#define G1_AHI    0
#define G1_ALO    10240
#define G1_BHI    20480
#define G1_BLO    25600
#define G1_STAGE  30720
#define G1_SMEM   (2 * G1_STAGE)
#define G1_NITER  (DIM1 / 32)     // 64

__global__ void __launch_bounds__(256) gemm1_tc(float* __restrict__ out) {
    // spare column: initialize out with the c0 bias (fused adds partials atomically)
    if (blockIdx.x == 13) {
        int t = blockIdx.y * 256 + threadIdx.x;      // 0..4095
        float c0 = g_c0[0];
        for (int i = t; i < OUTN; i += 4096) out[i] = c0;
        return;
    }

    extern __shared__ __align__(128) char sm[];
    const uint32_t smb = smem_u32(sm);
    const int tid  = threadIdx.x;
    const int lane = tid & 31;
    const int warp = tid >> 5;
    const int wm = warp >> 1;
    const int wn = warp & 1;
    const int mBase = blockIdx.x * 128;
    const int nBase = blockIdx.y * 64;

    int arow0 = mBase + (tid >> 2);
    int arow1 = mBase + ((tid + 256) >> 2);
    if (arow0 >= M1) arow0 = M1 - 1;
    if (arow1 >= M1) arow1 = M1 - 1;
    const int acb0 = tid & 3;
    const int acb1 = (tid + 256) & 3;
    const int brow = nBase + (tid >> 2);
    const int bcb  = tid & 3;

    auto load_stage = [&](int c, int st) {
        const int kc = c * 32;
        const uint32_t base = smb + st * G1_STAGE;
        cp16(base + G1_AHI + (tid >> 2) * G1_ROWB + acb0 * 16,
             g_x1hi + (size_t)arow0 * DIM1 + kc + acb0 * 8);
        cp16(base + G1_AHI + ((tid + 256) >> 2) * G1_ROWB + acb1 * 16,
             g_x1hi + (size_t)arow1 * DIM1 + kc + acb1 * 8);
        cp16(base + G1_ALO + (tid >> 2) * G1_ROWB + acb0 * 16,
             g_x1lo + (size_t)arow0 * DIM1 + kc + acb0 * 8);
        cp16(base + G1_ALO + ((tid + 256) >> 2) * G1_ROWB + acb1 * 16,
             g_x1lo + (size_t)arow1 * DIM1 + kc + acb1 * 8);
        cp16(base + G1_BHI + (tid >> 2) * G1_ROWB + bcb * 16,
             g_w1hi + (size_t)brow * DIM1 + kc + bcb * 8);
        cp16(base + G1_BLO + (tid >> 2) * G1_ROWB + bcb * 16,
             g_w1lo + (size_t)brow * DIM1 + kc + bcb * 8);
    };

    float acc[2][4][4];
    #pragma unroll
    for (int i = 0; i < 2; i++)
        #pragma unroll
        for (int j = 0; j < 4; j++)
            #pragma unroll
            for (int k = 0; k < 4; k++) acc[i][j][k] = 0.f;

    load_stage(0, 0); cp_commit();
    load_stage(1, 1); cp_commit();

    const int lrow  = lane & 15;
    const int lcol  = (lane >> 4) * 16;
    const int bn    = lane >> 2;
    const int bk4   = (lane & 3) * 4;

    for (int c = 0; c < G1_NITER; c++) {
        cp_wait1();
        __syncthreads();
        const uint32_t base = smb + (c & 1) * G1_STAGE;

        #pragma unroll
        for (int ks = 0; ks < 2; ks++) {
            const uint32_t kb = ks * 32;
            uint32_t ah[2][4], al[2][4];
            #pragma unroll
            for (int mt = 0; mt < 2; mt++) {
                uint32_t r = wm * 32 + mt * 16 + lrow;
                ldmx4(ah[mt][0], ah[mt][1], ah[mt][2], ah[mt][3],
                      base + G1_AHI + r * G1_ROWB + kb + lcol);
                ldmx4(al[mt][0], al[mt][1], al[mt][2], al[mt][3],
                      base + G1_ALO + r * G1_ROWB + kb + lcol);
            }
            uint32_t bhf[4][2], blf[4][2];
            #pragma unroll
            for (int nt = 0; nt < 4; nt++) {
                uint32_t r = wn * 32 + nt * 8 + bn;
                uint32_t a0 = base + G1_BHI + r * G1_ROWB + kb + bk4;
                uint32_t a1 = base + G1_BLO + r * G1_ROWB + kb + bk4;
                asm volatile("ld.shared.b32 %0, [%1];" : "=r"(bhf[nt][0]) : "r"(a0));
                asm volatile("ld.shared.b32 %0, [%1];" : "=r"(bhf[nt][1]) : "r"(a0 + 16));
                asm volatile("ld.shared.b32 %0, [%1];" : "=r"(blf[nt][0]) : "r"(a1));
                asm volatile("ld.shared.b32 %0, [%1];" : "=r"(blf[nt][1]) : "r"(a1 + 16));
            }
            #pragma unroll
            for (int mt = 0; mt < 2; mt++)
                #pragma unroll
                for (int nt = 0; nt < 4; nt++) {
                    float* d = acc[mt][nt];
                    mma_bf16(d[0], d[1], d[2], d[3],
                             ah[mt][0], ah[mt][1], ah[mt][2], ah[mt][3],
                             bhf[nt][0], bhf[nt][1]);
                    mma_bf16(d[0], d[1], d[2], d[3],
                             ah[mt][0], ah[mt][1], ah[mt][2], ah[mt][3],
                             blf[nt][0], blf[nt][1]);
                    mma_bf16(d[0], d[1], d[2], d[3],
                             al[mt][0], al[mt][1], al[mt][2], al[mt][3],
                             bhf[nt][0], bhf[nt][1]);
                }
        }
        __syncthreads();
        if (c + 2 < G1_NITER) load_stage(c + 2, c & 1);
        cp_commit();
    }

    const int crow = (lane >> 2);
    const int ccol = (lane & 3) * 2;
    #pragma unroll
    for (int mt = 0; mt < 2; mt++) {
        int m0 = mBase + wm * 32 + mt * 16 + crow;
        #pragma unroll
        for (int nt = 0; nt < 4; nt++) {
            int n = nBase + wn * 32 + nt * 8 + ccol;
            if (m0 < M1)
                *(float2*)(g_p1 + (size_t)m0 * ATTD + n) = make_float2(acc[mt][nt][0], acc[mt][nt][1]);
            if (m0 + 8 < M1)
                *(float2*)(g_p1 + (size_t)(m0 + 8) * ATTD + n) = make_float2(acc[mt][nt][2], acc[mt][nt][3]);
        }
    }
}

// ---------------- launch 4 (profiled): fused bilinear tanh reduce --------------
// Each block: (32p x 16l) tile, ONE 512-a half; 256 threads, 2 outputs/thread.
// alpha contribution = sum_a v[a]*(1 - 2*rcp(ex2(q*r)+1)) = -0.5*sum(sv) + sum(sv*rcp)
// with sv = -2*v.  Halves combined by atomicAdd onto c0-initialized out.
#define TPp 32
#define TLl 16
#define CAa 64

__global__ void __launch_bounds__(256) fused_kernel(float* __restrict__ out) {
    __shared__ float sp1T[CAa][TPp + 2];
    __shared__ float sp2T[CAa][TLl + 2];
    __shared__ float sv[CAa];

    const int tid = threadIdx.x;
    const int tx = tid & 15;        // p pair (2tx, 2tx+1)
    const int ty = tid >> 4;        // l (0..15)
    const int b    = blockIdx.z >> 1;
    const int half = blockIdx.z & 1;
    const int l0 = blockIdx.y * TLl;
    const int p0 = blockIdx.x * TPp;

    float acc0 = 0.f, acc1 = 0.f, vsum2 = 0.f;

    for (int cc = 0; cc < 8; cc++) {
        const int a0 = half * 512 + cc * CAa;
        // sp1T[a][p]: 64a x 32p = 2048 / 256 thr = 8 each (a = idx&63 -> coalesced)
        #pragma unroll
        for (int i = 0; i < 8; i++) {
            int idx = tid + i * 256;
            int a = idx & 63;
            int p = idx >> 6;
            int gp = p0 + p;
            float v = 0.f;
            if (gp < PP) v = g_p1[((b * PP + gp) << 10) + a0 + a];
            sp1T[a][p] = v;
        }
        // sp2T[a][l]: 64a x 16l = 1024 / 256 = 4 each
        #pragma unroll
        for (int i = 0; i < 4; i++) {
            int idx = tid + i * 256;
            int a = idx & 63;
            int l = idx >> 6;
            sp2T[a][l] = g_p2[((b * LL + l0 + l) << 10) + a0 + a];
        }
        if (tid < CAa) sv[tid] = -2.0f * g_v[a0 + tid];
        __syncthreads();

        #pragma unroll 8
        for (int k = 0; k < CAa; k++) {
            float2 rr = *(const float2*)&sp1T[k][2 * tx];
            float q  = sp2T[k][ty];
            float vv = sv[k];
            vsum2 += vv;
            float e0, e1, r0, r1;
            asm("ex2.approx.f32 %0, %1;" : "=f"(e0) : "f"(q * rr.x));
            asm("ex2.approx.f32 %0, %1;" : "=f"(e1) : "f"(q * rr.y));
            float d0 = e0 + 1.0f, d1 = e1 + 1.0f;
            asm("rcp.approx.f32 %0, %1;" : "=f"(r0) : "f"(d0));
            asm("rcp.approx.f32 %0, %1;" : "=f"(r1) : "f"(d1));
            acc0 = fmaf(vv, r0, acc0);
            acc1 = fmaf(vv, r1, acc1);
        }
        __syncthreads();
    }

    const float base = -0.5f * vsum2;
    const int p = p0 + 2 * tx;
    const int l = l0 + ty;
    float* orow = out + (b * LL + l) * PP;
    if (p < PP)     atomicAdd(orow + p,     base + acc0);
    if (p + 1 < PP) atomicAdd(orow + p + 1, base + acc1);
}

// ---------------- launch ----------------
extern "C" void kernel_launch(void* const* d_in, const int* in_sizes, int n_in,
                              void* d_out, int out_size) {
    const float* x1 = (const float*)d_in[0];
    const float* x2 = (const float*)d_in[1];
    const float* W1 = (const float*)d_in[2];
    const float* W2 = (const float*)d_in[3];
    const float* Wh = (const float*)d_in[4];
    const float* bh = (const float*)d_in[5];
    const float* wt = (const float*)d_in[6];
    const float* bt = (const float*)d_in[7];
    float* out = (float*)d_out;

    static int smem_set = 0;
    if (!smem_set) {
        cudaFuncSetAttribute(gemm1_tc, cudaFuncAttributeMaxDynamicSharedMemorySize, G1_SMEM);
        smem_set = 1;
    }

    // 1: bf16 splits (x1 + W1)
    k_split_all<<<X1_BLKS + W1_BLKS, 256>>>(x1, W1);
    // 2: p2 GEMM + v + c0
    {
        dim3 grid(21, ATTD / 64);
        gemm2pre<<<grid, 128>>>(x2, W2, Wh, wt, bh, bt);
    }
    // 3: p1 via mma.sync bf16 3-term (+ out init in spare column)
    {
        dim3 grid(14, ATTD / 64);
        gemm1_tc<<<grid, 256, G1_SMEM>>>(out);
    }
    // 4: fused bilinear tanh reduce  (ncu-profiled slot)
    {
        dim3 grid((PP + TPp - 1) / TPp, LL / TLl, BB * 2);
        fused_kernel<<<grid, 256>>>(out);
    }
}